// round 7
// baseline (speedup 1.0000x reference)
#include <cuda_runtime.h>
#include <cstdint>
#include <cstddef>

typedef unsigned long long u64;

// ---------------------------------------------------------------------------
// Shapes: B=4, SQ=2048, SK=1024, D=1024. All GEMM K = 1024.
// ---------------------------------------------------------------------------

// scratch (device globals; allocation forbidden)
__device__ __align__(256) float g_k  [4ull * 1024 * 1024];   // k  [b*1024+s][d]
__device__ __align__(256) float g_vt [1024ull * 4096];       // vT [d][b*1024+s]
__device__ __align__(256) float g_qy [8192ull * 1024];       // qy
__device__ __align__(256) float g_inv[8192ull * 1024];       // inv
__device__ __align__(256) float g_qk [8192ull * 1024];       // qk / attn

__device__ __forceinline__ u64 pack_dup(float a) {
    u64 r;
    asm("mov.b64 %0, {%1, %1};" : "=l"(r) : "f"(a));
    return r;
}
__device__ __forceinline__ void fma2(u64 &d, u64 a, u64 b) {
    asm("fma.rn.f32x2 %0, %1, %2, %0;" : "+l"(d) : "l"(a), "l"(b));
}

#define RS   264                 // smem row stride (floats)
#define BUFS (8 * RS)            // one k-slab buffer (floats)

// ---------------------------------------------------------------------------
// Core: C[m0+128, n0+256] = sum_k A[m,k] * B[n,k]  (NT), fp32, K=1024.
// 256 threads; thread (tx=tid&15, ty=tid>>4) owns rows m0+8ty..+7 and
// cols n0+16tx..+15. Accumulate in u64-packed f32x2 (FFMA2).
// Smem: A stored DUPLICATED per element ([k][2m],[k][2m+1] equal);
//       B stored permuted: col L(n) = ((n>>2)&3)*64 + (n>>4)*4 + (n&3)
//       so per-kk B loads are contiguous across tx (conflict-free).
// epi: 0 = +bias[n] | 1 = +bias[m] | 2 = /= aux[r*ldC+col] | 3 = none
// ---------------------------------------------------------------------------
__device__ __forceinline__ void run_gemm(
    const float* __restrict__ A, int ldA,
    const float* __restrict__ B, int ldB,
    float* __restrict__ C, int ldC,
    const float* __restrict__ aux, int epi,
    int m0, int n0, float* sA, float* sB)
{
    const int tid  = threadIdx.x;
    const int tx   = tid & 15, ty = tid >> 4;
    const int half = tid >> 1, kq = (tid & 1) * 4;

    const float* Ag  = A + (size_t)(m0 + half) * ldA + kq;
    const float* Bg0 = B + (size_t)(n0 + half) * ldB + kq;
    const float* Bg1 = B + (size_t)(n0 + 128 + half) * ldB + kq;

    const int Ln0 = ((half >> 2) & 3) * 64 + (half >> 4) * 4 + (half & 3);
    const int nr1 = half + 128;
    const int Ln1 = ((nr1 >> 2) & 3) * 64 + (nr1 >> 4) * 4 + (nr1 & 3);

    u64 acc[8][8];
    #pragma unroll
    for (int i = 0; i < 8; i++)
        #pragma unroll
        for (int j = 0; j < 8; j++) acc[i][j] = 0ull;

    float4 ra  = *(const float4*)Ag;
    float4 rb0 = *(const float4*)Bg0;
    float4 rb1 = *(const float4*)Bg1;

    #pragma unroll 2
    for (int s = 0; s < 128; s++) {
        const int buf = s & 1;

        // ---- store staged slab into smem ----
        {
            float* ab = sA + buf * BUFS + kq * RS + 2 * half;
            *(u64*)(ab + 0 * RS) = pack_dup(ra.x);
            *(u64*)(ab + 1 * RS) = pack_dup(ra.y);
            *(u64*)(ab + 2 * RS) = pack_dup(ra.z);
            *(u64*)(ab + 3 * RS) = pack_dup(ra.w);
            float* bb = sB + buf * BUFS + kq * RS;
            bb[0 * RS + Ln0] = rb0.x;
            bb[1 * RS + Ln0] = rb0.y;
            bb[2 * RS + Ln0] = rb0.z;
            bb[3 * RS + Ln0] = rb0.w;
            bb[0 * RS + Ln1] = rb1.x;
            bb[1 * RS + Ln1] = rb1.y;
            bb[2 * RS + Ln1] = rb1.z;
            bb[3 * RS + Ln1] = rb1.w;
        }
        __syncthreads();

        // ---- stage next slab (latency hidden under compute) ----
        if (s + 1 < 128) {
            const int k0 = (s + 1) * 8;
            ra  = *(const float4*)(Ag  + k0);
            rb0 = *(const float4*)(Bg0 + k0);
            rb1 = *(const float4*)(Bg1 + k0);
        }

        // ---- compute 8 kk ----
        const float* ca = sA + buf * BUFS + 16 * ty;
        const float* cb = sB + buf * BUFS + 4 * tx;
        #pragma unroll
        for (int kk = 0; kk < 8; kk++) {
            ulonglong2 aq[4], bq[4];
            #pragma unroll
            for (int p = 0; p < 4; p++)
                aq[p] = *(const ulonglong2*)(ca + kk * RS + p * 4);
            #pragma unroll
            for (int p = 0; p < 4; p++)
                bq[p] = *(const ulonglong2*)(cb + kk * RS + p * 64);
            u64 ad[8], bv[8];
            #pragma unroll
            for (int p = 0; p < 4; p++) {
                ad[2 * p] = aq[p].x; ad[2 * p + 1] = aq[p].y;
                bv[2 * p] = bq[p].x; bv[2 * p + 1] = bq[p].y;
            }
            #pragma unroll
            for (int i = 0; i < 8; i++)
                #pragma unroll
                for (int j = 0; j < 8; j++)
                    fma2(acc[i][j], ad[i], bv[j]);
        }
    }

    // ---- epilogue ----
    const int cbase = n0 + 16 * tx;
    float bn[16];
    if (epi == 0) {
        #pragma unroll
        for (int p = 0; p < 4; p++)
            *(float4*)&bn[p * 4] = *(const float4*)(aux + cbase + p * 4);
    }
    #pragma unroll
    for (int i = 0; i < 8; i++) {
        const int r = m0 + 8 * ty + i;
        float v[16];
        #pragma unroll
        for (int j = 0; j < 8; j++) {
            float2 f = *reinterpret_cast<float2*>(&acc[i][j]);
            v[2 * j]     = f.x;
            v[2 * j + 1] = f.y;
        }
        if (epi == 0) {
            #pragma unroll
            for (int j = 0; j < 16; j++) v[j] += bn[j];
        } else if (epi == 1) {
            const float bm = aux[r];
            #pragma unroll
            for (int j = 0; j < 16; j++) v[j] += bm;
        } else if (epi == 2) {
            const float* dx = aux + (size_t)r * ldC + cbase;
            #pragma unroll
            for (int p = 0; p < 4; p++) {
                const float4 d = *(const float4*)(dx + p * 4);
                v[p * 4 + 0] /= d.x;
                v[p * 4 + 1] /= d.y;
                v[p * 4 + 2] /= d.z;
                v[p * 4 + 3] /= d.w;
            }
        }
        float* cp = C + (size_t)r * ldC + cbase;
        #pragma unroll
        for (int p = 0; p < 4; p++)
            *(float4*)(cp + p * 4) = *(float4*)&v[p * 4];
    }
}

// ---------------------------------------------------------------------------
// Fused kernel: the 4 independent linears in one grid (768 CTAs).
//   [0,128)   k   = y @ W2^T + b2      M=4096, N=1024: 32 x 4 tiles
//   [128,256) vT  = W3 @ y^T + b3[m]   M=1024, N=4096: 8 x 16 tiles, ldC=4096
//   [256,512) qy  = x @ W4^T + b4      M=8192, N=1024: 64 x 4 tiles
//   [512,768) inv = x @ W5^T + b5      M=8192, N=1024: 64 x 4 tiles
// ---------------------------------------------------------------------------
__global__ void __launch_bounds__(256) k_fused(
    const float* __restrict__ x, const float* __restrict__ y,
    const float* __restrict__ W2, const float* __restrict__ b2,
    const float* __restrict__ W3, const float* __restrict__ b3,
    const float* __restrict__ W4, const float* __restrict__ b4,
    const float* __restrict__ W5, const float* __restrict__ b5,
    float* __restrict__ gk, float* __restrict__ gvt,
    float* __restrict__ gqy, float* __restrict__ ginv)
{
    __shared__ __align__(16) float sA[2 * BUFS];
    __shared__ __align__(16) float sB[2 * BUFS];

    const int t = blockIdx.x;
    const float *A, *B, *aux;
    float* C;
    int ldC, epi, m0, n0;

    if (t < 128) {
        A = y;  B = W2; C = gk;   aux = b2; ldC = 1024; epi = 0;
        m0 = (t >> 2) * 128; n0 = (t & 3) * 256;
    } else if (t < 256) {
        const int u = t - 128;
        A = W3; B = y;  C = gvt;  aux = b3; ldC = 4096; epi = 1;
        m0 = (u >> 4) * 128; n0 = (u & 15) * 256;
    } else if (t < 512) {
        const int u = t - 256;
        A = x;  B = W4; C = gqy;  aux = b4; ldC = 1024; epi = 0;
        m0 = (u >> 2) * 128; n0 = (u & 3) * 256;
    } else {
        const int u = t - 512;
        A = x;  B = W5; C = ginv; aux = b5; ldC = 1024; epi = 0;
        m0 = (u >> 2) * 128; n0 = (u & 3) * 256;
    }
    run_gemm(A, 1024, B, 1024, C, ldC, aux, epi, m0, n0, sA, sB);
}

// qk = (qy @ k^T) / inv, per batch z
__global__ void __launch_bounds__(256) k_qk(
    const float* __restrict__ gqy, const float* __restrict__ gk,
    const float* __restrict__ ginv, float* __restrict__ gqk)
{
    __shared__ __align__(16) float sA[2 * BUFS];
    __shared__ __align__(16) float sB[2 * BUFS];
    const size_t z = blockIdx.z;
    run_gemm(gqy + z * (2048ull * 1024), 1024,
             gk  + z * (1024ull * 1024), 1024,
             gqk + z * (2048ull * 1024), 1024,
             ginv + z * (2048ull * 1024), 2,
             blockIdx.y * 128, blockIdx.x * 256, sA, sB);
}

// out = attn @ vT^T, per batch z (B row n lives at gvt + z*1024 + n*4096)
__global__ void __launch_bounds__(256) k_av(
    const float* __restrict__ gqk, const float* __restrict__ gvt,
    float* __restrict__ out)
{
    __shared__ __align__(16) float sA[2 * BUFS];
    __shared__ __align__(16) float sB[2 * BUFS];
    const size_t z = blockIdx.z;
    run_gemm(gqk + z * (2048ull * 1024), 1024,
             gvt + z * 1024, 4096,
             out + z * (2048ull * 1024), 1024,
             nullptr, 3,
             blockIdx.y * 128, blockIdx.x * 256, sA, sB);
}

// ---------------------------------------------------------------------------
// Row softmax over 1024, in place. 1 block/row, 256 threads. (validated R1)
// ---------------------------------------------------------------------------
__global__ void __launch_bounds__(256) softmax1024(float* __restrict__ data)
{
    float* p = data + (size_t)blockIdx.x * 1024;
    const int t = threadIdx.x, lane = t & 31, warp = t >> 5;
    __shared__ float red[8];
    __shared__ float stat[2];

    float4 x = *((const float4*)p + t);
    float m = fmaxf(fmaxf(x.x, x.y), fmaxf(x.z, x.w));
    #pragma unroll
    for (int o = 16; o > 0; o >>= 1) m = fmaxf(m, __shfl_xor_sync(~0u, m, o));
    if (lane == 0) red[warp] = m;
    __syncthreads();
    if (t == 0) {
        float mm = red[0];
        #pragma unroll
        for (int i = 1; i < 8; i++) mm = fmaxf(mm, red[i]);
        stat[0] = mm;
    }
    __syncthreads();
    const float bm = stat[0];
    x.x = __expf(x.x - bm); x.y = __expf(x.y - bm);
    x.z = __expf(x.z - bm); x.w = __expf(x.w - bm);
    float s = (x.x + x.y) + (x.z + x.w);
    #pragma unroll
    for (int o = 16; o > 0; o >>= 1) s += __shfl_xor_sync(~0u, s, o);
    __syncthreads();
    if (lane == 0) red[warp] = s;
    __syncthreads();
    if (t == 0) {
        float ss = red[0];
        #pragma unroll
        for (int i = 1; i < 8; i++) ss += red[i];
        stat[1] = 1.0f / ss;
    }
    __syncthreads();
    const float r = stat[1];
    x.x *= r; x.y *= r; x.z *= r; x.w *= r;
    *((float4*)p + t) = x;
}

// ---------------------------------------------------------------------------
static float* symaddr(const void* s) {
    void* p = nullptr;
    cudaGetSymbolAddress(&p, s);
    return (float*)p;
}

extern "C" void kernel_launch(void* const* d_in, const int* in_sizes, int n_in,
                              void* d_out, int out_size)
{
    (void)in_sizes; (void)n_in; (void)out_size;
    const float* x  = (const float*)d_in[0];
    const float* y  = (const float*)d_in[1];
    const float* W2 = (const float*)d_in[4];  const float* b2 = (const float*)d_in[5];
    const float* W3 = (const float*)d_in[6];  const float* b3 = (const float*)d_in[7];
    const float* W4 = (const float*)d_in[8];  const float* b4 = (const float*)d_in[9];
    const float* W5 = (const float*)d_in[10]; const float* b5 = (const float*)d_in[11];
    float* out = (float*)d_out;

    float* gk   = symaddr(g_k);
    float* gvt  = symaddr(g_vt);
    float* gqy  = symaddr(g_qy);
    float* ginv = symaddr(g_inv);
    float* gqk  = symaddr(g_qk);

    // 1) the four independent linears, fused into one launch (768 tiles)
    k_fused<<<768, 256>>>(x, y, W2, b2, W3, b3, W4, b4, W5, b5,
                          gk, gvt, gqy, ginv);

    // 2) qk = (qy @ k^T) / inv
    k_qk<<<dim3(4, 16, 4), 256>>>(gqy, gk, ginv, gqk);

    // 3) softmax rows (in place)
    softmax1024<<<8192, 256>>>(gqk);

    // 4) out = attn @ v
    k_av<<<dim3(4, 16, 4), 256>>>(gqk, gvt, out);
}